// round 15
// baseline (speedup 1.0000x reference)
#include <cuda_runtime.h>
#include <cstdint>

// TemporalScaledDotProductforCrossAttention — GB300 fused kernel, v7.
// ONE WARP OWNS ONE SITE (all 4 variants): lane = v*8 + qg*2 + h,
//   v=variant(ff,fs,sf,ss), qg=row-group (3 q-rows each), h=D-half.
// CTA = 4 warps = 4 sites (all SMSPs busy). 92KB dynamic smem -> 2 CTAs/SM.
// B-tile bases distinct mod 4 => every B LDS is 8 distinct 16B = 1 wavefront.
// Vf/Vs bases mod 8 = {0,6}  => every V LDS conflict-free.
// No block barriers at all: staging + flow build + compute are warp-local.

static constexpr int QF  = 0;      // stride-17 tiles, 204 f4 each
static constexpr int KF  = 205;    // mod4 = 1
static constexpr int KS  = 410;    // mod4 = 2
static constexpr int QFS = 615;    // mod4 = 3
static constexpr int QS  = 820;
static constexpr int VF  = 1024;   // mod8 = 0
static constexpr int VS  = 1230;   // mod8 = 6
static constexpr int MSK = 1434;   // 36 f4 = 144 ints
static constexpr int SITE_F4 = 1472;            // mod 8 == 0 (preserves banks)
static constexpr int SMEM_BYTES = 4 * SITE_F4 * 16;   // 94208

__device__ __forceinline__ unsigned long long fma2(unsigned long long a,
                                                   unsigned long long b,
                                                   unsigned long long c) {
    unsigned long long d;
    asm("fma.rn.f32x2 %0, %1, %2, %3;" : "=l"(d) : "l"(a), "l"(b), "l"(c));
    return d;
}
__device__ __forceinline__ unsigned long long pack2(float x, float y) {
    unsigned long long r;
    asm("mov.b64 %0, {%1, %2};" : "=l"(r) : "f"(x), "f"(y));
    return r;
}
__device__ __forceinline__ float2 unpack2(unsigned long long v) {
    float2 r;
    asm("mov.b64 {%0, %1}, %2;" : "=f"(r.x), "=f"(r.y) : "l"(v));
    return r;
}
__device__ __forceinline__ void cp16(uint32_t smem_addr, const void* gptr) {
    asm volatile("cp.async.cg.shared.global [%0], [%1], 16;"
                 :: "r"(smem_addr), "l"(gptr));
}

__global__ __launch_bounds__(128, 2)
void tsdp_kernel(const float* __restrict__ Qf, const float* __restrict__ Kf,
                 const float* __restrict__ Vf, const float* __restrict__ Qs,
                 const float* __restrict__ Ks, const float* __restrict__ Vs,
                 const float* __restrict__ Kj, const float* __restrict__ Vfp,
                 const int* __restrict__ mask, float* __restrict__ out,
                 int nsite)
{
    extern __shared__ float4 T[];

    const int tid  = threadIdx.x;
    const int warp = tid >> 5;
    const int lane = tid & 31;
    const int site = blockIdx.x * 4 + warp;

    float4* Ts = T + warp * SITE_F4;
    const uint32_t sb = (uint32_t)__cvta_generic_to_shared(Ts);

    // ---- Stage this warp's site via cp.async (6 tiles + mask) ----
    {
        const long long gbase = (long long)site * 192;
        #pragma unroll
        for (int rep = 0; rep < 6; rep++) {
            int f  = lane + rep * 32;              // [0, 192)
            int r  = f >> 4, cc = f & 15;
            uint32_t sa = sb + (uint32_t)(r * 17 + cc) * 16u;
            long long g = gbase + f;
            cp16(sa + QF * 16u, (const float4*)Qf + g);
            cp16(sa + KF * 16u, (const float4*)Kf + g);
            cp16(sa + KS * 16u, (const float4*)Ks + g);
            cp16(sa + QS * 16u, (const float4*)Qs + g);
            cp16(sa + VF * 16u, (const float4*)Vf + g);
            cp16(sa + VS * 16u, (const float4*)Vs + g);
        }
        // mask: 36 f4 (144 ints), per-warp copy
        cp16(sb + (MSK + lane) * 16u, (const float4*)mask + lane);
        if (lane < 4)
            cp16(sb + (MSK + 32 + lane) * 16u, (const float4*)mask + 32 + lane);
        asm volatile("cp.async.commit_group;" ::: "memory");
        asm volatile("cp.async.wait_group 0;" ::: "memory");
        __syncwarp();
    }

    // ---- Build flow-speed tile (QFS) from resident QS tile (warp-local) ----
    #pragma unroll
    for (int rep = 0; rep < 6; rep++) {
        int f  = lane + rep * 32;
        int r  = f >> 4, cc = f & 15;
        int i17 = r * 17 + cc;
        float4 v = Ts[QS + i17];
        float kj  = __ldg(Kj + r);
        float inv = 1.0f / (__ldg(Vfp + r) + 1e-5f);
        float4 w;
        w.x = kj * (v.x - (v.x * v.x) * inv);
        w.y = kj * (v.y - (v.y * v.y) * inv);
        w.z = kj * (v.z - (v.z * v.z) * inv);
        w.w = kj * (v.w - (v.w * v.w) * inv);
        Ts[QFS + i17] = w;
    }
    __syncwarp();

    // ---- Lane roles ----
    const int v   = lane >> 3;          // variant: 0 ff, 1 fs, 2 sf, 3 ss
    const int qg  = (lane >> 1) & 3;    // row group (3 rows)
    const int h   = lane & 1;           // D-half
    const int rot = 4 * h;
    const int q0  = 3 * qg, q1 = q0 + 1, q2 = q0 + 2;

    int aO, bO, vO;                      // tile offsets (f4)
    if      (v == 0) { aO = QF; bO = KF;  vO = VF; }   // ff: Qf·Kf^T  -> Vf
    else if (v == 1) { aO = KF; bO = QFS; vO = VF; }   // fs: Kf·Qfs^T -> Vf
    else if (v == 2) { aO = KS; bO = QF;  vO = VS; }   // sf: Ks·Qf^T  -> Vs
    else             { aO = QS; bO = KS;  vO = VS; }   // ss: Qs·Ks^T  -> Vs

    const ulonglong2* A2 = (const ulonglong2*)(Ts + aO);
    const ulonglong2* B2 = (const ulonglong2*)(Ts + bO);
    const ulonglong2* V2 = (const ulonglong2*)(Ts + vO);
    const int* smask = (const int*)(Ts + MSK);

    // ---- Scores: g=3 rows per lane; every B chunk feeds 3 rows ----
    float s0[12], s1[12], s2[12];
    #pragma unroll
    for (int k = 0; k < 12; k++) { s0[k] = 0.f; s1[k] = 0.f; s2[k] = 0.f; }

    #pragma unroll
    for (int ch = 0; ch < 2; ch++) {
        ulonglong2 a0[4], a1[4], a2[4];
        int jj[4];
        #pragma unroll
        for (int i = 0; i < 4; i++) {
            jj[i] = (ch * 4 + i + rot) & 7;
            a0[i] = A2[q0 * 17 + h * 8 + jj[i]];
            a1[i] = A2[q1 * 17 + h * 8 + jj[i]];
            a2[i] = A2[q2 * 17 + h * 8 + jj[i]];
        }
        #pragma unroll
        for (int k = 0; k < 12; k++) {
            unsigned long long acc0 = 0ULL, acc1 = 0ULL, acc2 = 0ULL;
            #pragma unroll
            for (int i = 0; i < 4; i++) {
                ulonglong2 b = B2[k * 17 + h * 8 + jj[i]];  // 1 wavefront
                acc0 = fma2(a0[i].x, b.x, acc0);
                acc0 = fma2(a0[i].y, b.y, acc0);
                acc1 = fma2(a1[i].x, b.x, acc1);
                acc1 = fma2(a1[i].y, b.y, acc1);
                acc2 = fma2(a2[i].x, b.x, acc2);
                acc2 = fma2(a2[i].y, b.y, acc2);
            }
            float2 p0 = unpack2(acc0), p1 = unpack2(acc1), p2 = unpack2(acc2);
            s0[k] += p0.x + p0.y;
            s1[k] += p1.x + p1.y;
            s2[k] += p2.x + p2.y;
        }
    }

    // cross-half reduce + scale + exact mask select
    #pragma unroll
    for (int k = 0; k < 12; k++) {
        float w0 = s0[k] + __shfl_xor_sync(0xffffffffu, s0[k], 1);
        float w1 = s1[k] + __shfl_xor_sync(0xffffffffu, s1[k], 1);
        float w2 = s2[k] + __shfl_xor_sync(0xffffffffu, s2[k], 1);
        s0[k] = (smask[q0 * 12 + k] == 1) ? -1e9f : w0 * 0.125f;
        s1[k] = (smask[q1 * 12 + k] == 1) ? -1e9f : w1 * 0.125f;
        s2[k] = (smask[q2 * 12 + k] == 1) ? -1e9f : w2 * 0.125f;
    }

    // ---- Softmax per row; pre-scale by 1/sum ----
    float m0 = s0[0], m1 = s1[0], m2 = s2[0];
    #pragma unroll
    for (int k = 1; k < 12; k++) {
        m0 = fmaxf(m0, s0[k]); m1 = fmaxf(m1, s1[k]); m2 = fmaxf(m2, s2[k]);
    }
    float t0 = 0.f, t1 = 0.f, t2 = 0.f;
    #pragma unroll
    for (int k = 0; k < 12; k++) {
        s0[k] = __expf(s0[k] - m0); t0 += s0[k];
        s1[k] = __expf(s1[k] - m1); t1 += s1[k];
        s2[k] = __expf(s2[k] - m2); t2 += s2[k];
    }
    const float r0 = 1.0f / t0, r1 = 1.0f / t1, r2 = 1.0f / t2;
    #pragma unroll
    for (int k = 0; k < 12; k++) { s0[k] *= r0; s1[k] *= r1; s2[k] *= r2; }

    // ---- Output (k-outer): every V chunk feeds 3 rows ----
    ulonglong2 c0[8], c1[8], c2[8];
    #pragma unroll
    for (int i = 0; i < 8; i++) {
        c0[i].x = c0[i].y = 0ULL; c1[i].x = c1[i].y = 0ULL; c2[i].x = c2[i].y = 0ULL;
    }
    #pragma unroll
    for (int k = 0; k < 12; k++) {
        unsigned long long z0 = pack2(s0[k], s0[k]);
        unsigned long long z1 = pack2(s1[k], s1[k]);
        unsigned long long z2 = pack2(s2[k], s2[k]);
        #pragma unroll
        for (int i = 0; i < 8; i++) {
            ulonglong2 vv = V2[k * 17 + h * 8 + ((i + rot) & 7)];  // 1 wavefront
            c0[i].x = fma2(z0, vv.x, c0[i].x);  c0[i].y = fma2(z0, vv.y, c0[i].y);
            c1[i].x = fma2(z1, vv.x, c1[i].x);  c1[i].y = fma2(z1, vv.y, c1[i].y);
            c2[i].x = fma2(z2, vv.x, c2[i].x);  c2[i].y = fma2(z2, vv.y, c2[i].y);
        }
    }

    // ---- Store 3 rows (un-rotate); quarters ordered (ff, fs, sf, ss) = v ----
    float4* ob = (float4*)out + ((long long)v * nsite + site) * 192 + h * 8;
    float4* o0 = ob + q0 * 16;
    float4* o1 = ob + q1 * 16;
    float4* o2 = ob + q2 * 16;
    #pragma unroll
    for (int i = 0; i < 8; i++) {
        int j = (i + rot) & 7;
        float2 a, b;
        a = unpack2(c0[i].x); b = unpack2(c0[i].y); o0[j] = make_float4(a.x, a.y, b.x, b.y);
        a = unpack2(c1[i].x); b = unpack2(c1[i].y); o1[j] = make_float4(a.x, a.y, b.x, b.y);
        a = unpack2(c2[i].x); b = unpack2(c2[i].y); o2[j] = make_float4(a.x, a.y, b.x, b.y);
    }
}

extern "C" void kernel_launch(void* const* d_in, const int* in_sizes, int n_in,
                              void* d_out, int out_size) {
    const int nsite = in_sizes[0] / 768;   // B*H*L1 = 39296 (divisible by 4)
    cudaFuncSetAttribute(tsdp_kernel,
                         cudaFuncAttributeMaxDynamicSharedMemorySize, SMEM_BYTES);
    tsdp_kernel<<<nsite / 4, 128, SMEM_BYTES>>>(
        (const float*)d_in[0], (const float*)d_in[1], (const float*)d_in[2],
        (const float*)d_in[3], (const float*)d_in[4], (const float*)d_in[5],
        (const float*)d_in[6], (const float*)d_in[7],
        (const int*)d_in[8],
        (float*)d_out, nsite);
}